// round 17
// baseline (speedup 1.0000x reference)
#include <cuda_runtime.h>

// Problem constants
#define B_  4
#define C_  16
#define H_  64
#define W_  64
#define F_  32
#define CC  4            // channels per smem chunk (4 chunks)
#define NR  6            // pair-row slots per channel (r = 0..5)
#define XPITCH 68        // doubles per slot row: logical cols -1..64 at phys 0..65, +2 pad
#define SLOT (NR * XPITCH)
#define NTHREADS 256

typedef unsigned long long ull;

__device__ __forceinline__ float frcp(float q) {
    float r;
    asm("rcp.approx.f32 %0, %1;" : "=f"(r) : "f"(q));
    return r;
}
__device__ __forceinline__ ull pack2(float lo, float hi) {
    ull r;
    asm("mov.b64 %0, {%1, %2};" : "=l"(r) : "f"(lo), "f"(hi));
    return r;
}
__device__ __forceinline__ void unpack2(ull v, float& lo, float& hi) {
    asm("mov.b64 {%0, %1}, %2;" : "=f"(lo), "=f"(hi) : "l"(v));
}
__device__ __forceinline__ ull fma2(ull a, ull b, ull c) {
    ull d;
    asm("fma.rn.f32x2 %0, %1, %2, %3;" : "=l"(d) : "l"(a), "l"(b), "l"(c));
    return d;
}
__device__ __forceinline__ ull mul2(ull a, ull b) {
    ull d;
    asm("mul.rn.f32x2 %0, %1, %2;" : "=l"(d) : "l"(a), "l"(b));
    return d;
}

// Two packed rational taps, explicitly interleaved (4 chains, 4 MUFUs batched).
__device__ __forceinline__ void eval_tap2(ull xpL, ull xpR,
                                          ull A5, ull A4, ull A3, ull A2, ull A1, ull A0,
                                          ull B4, ull B3, ull B2, ull B1,
                                          ull& accL, ull& accR)
{
    ull PL = fma2(A5, xpL, A4);
    ull PR = fma2(A5, xpR, A4);
    ull SL = fma2(B4, xpL, B3);
    ull SR = fma2(B4, xpR, B3);
    PL = fma2(PL, xpL, A3);
    PR = fma2(PR, xpR, A3);
    SL = fma2(SL, xpL, B2);
    SR = fma2(SR, xpR, B2);
    PL = fma2(PL, xpL, A2);
    PR = fma2(PR, xpR, A2);
    SL = fma2(SL, xpL, B1);
    SR = fma2(SR, xpR, B1);
    PL = fma2(PL, xpL, A1);
    PR = fma2(PR, xpR, A1);
    const ull SxL = mul2(SL, xpL);
    const ull SxR = mul2(SR, xpR);
    PL = fma2(PL, xpL, A0);
    PR = fma2(PR, xpR, A0);

    float sL0, sL1, sR0, sR1;
    unpack2(SxL, sL0, sL1);
    unpack2(SxR, sR0, sR1);
    const float rL0 = frcp(1.0f + fabsf(sL0));
    const float rL1 = frcp(1.0f + fabsf(sL1));
    const float rR0 = frcp(1.0f + fabsf(sR0));
    const float rR1 = frcp(1.0f + fabsf(sR1));
    accL = fma2(PL, pack2(rL0, rL1), accL);
    accR = fma2(PR, pack2(rR0, rR1), accR);
}

__global__ __launch_bounds__(NTHREADS, 5)
void kaconv_kernel(const float* __restrict__ x,
                   const float* __restrict__ nums,
                   const float* __restrict__ denoms,
                   float* __restrict__ out)
{
    // Coeffs duplicated into f32x2 double slots, Horner order per (c,k):
    // [a5 a4 | a3 a2 | a1 a0 | b4 b3 | b2 b1]  (5 x double2)
    __shared__ __align__(16) double scf[C_ * 9 * 10];   // 11520 B
    // Pre-packed row-pair tile: slot (c, r, p) = pack(x[gy0+r-1][p-1], x[gy0+r+3][p-1])
    __shared__ double spx[CC * SLOT];                    // 13056 B  (total 24576 B)

    const int tx  = threadIdx.x;        // 0..31
    const int ty  = threadIdx.y;        // 0..7 (warp id)
    const int tid = ty * 32 + tx;
    const int f   = blockIdx.z & (F_ - 1);
    const int b   = blockIdx.z >> 5;
    const int gy0 = blockIdx.y * 8;     // 8 output rows per block, full 64-col width

    // ---- stage Pade coefficients for filter f (144 (c,k) slots) ----
    for (int i = tid; i < C_ * 9; i += NTHREADS) {
        const float* np = nums   + (size_t)f * (C_ * 9 * 6) + i * 6;
        const float* dp = denoms + (size_t)f * (C_ * 9 * 4) + i * 4;
        double* dst = scf + i * 10;
        float a0 = np[0], a1 = np[1], a2 = np[2], a3 = np[3], a4 = np[4], a5 = np[5];
        float b1 = dp[0], b2 = dp[1], b3 = dp[2], b4 = dp[3];
        dst[0] = __longlong_as_double((long long)pack2(a5, a5));
        dst[1] = __longlong_as_double((long long)pack2(a4, a4));
        dst[2] = __longlong_as_double((long long)pack2(a3, a3));
        dst[3] = __longlong_as_double((long long)pack2(a2, a2));
        dst[4] = __longlong_as_double((long long)pack2(a1, a1));
        dst[5] = __longlong_as_double((long long)pack2(a0, a0));
        dst[6] = __longlong_as_double((long long)pack2(b4, b4));
        dst[7] = __longlong_as_double((long long)pack2(b3, b3));
        dst[8] = __longlong_as_double((long long)pack2(b2, b2));
        dst[9] = __longlong_as_double((long long)pack2(b1, b1));
    }

    // Thread owns: row pair (gy0+ty%4, +4) ... mapping: pair-row pr = ty & 3,
    // column group = ty >> 2 (cols tx / tx+32 handled by two half-blocks? No—
    // keep R4 mapping: pr = ty (0..3 twice? ty is 0..7).
    // Mapping: pair-row pr = ty & 3; column col = tx + 32*(ty >> 2).
    const int pr  = ty & 3;
    const int cg  = ty >> 2;            // 0 or 1
    const int col = tx + cg * 32;       // 0..63

    ull accL = 0ull;   // col, rows (gy0+pr, gy0+pr+4)  -- single acc pair per... 
    ull accR = 0ull;   // second accumulator: columns are split by warp, so use
                       // a SECOND pair-row instead: pr and pr? No: use k-split.
    // Each thread owns ONE column (col) and TWO row-pairs would need pr+4>5.
    // Instead: thread owns (pr, col) only -> 2 outputs. 256 threads x 2 = 512
    // outputs = half the tile. So each block covers 4 output rows? No --
    // revert: thread owns row-pair pr at columns col (2 outputs), block tile
    // = 8 rows x 64 cols = 512 outputs with 256 threads x 2 outputs. Grid y = 8.
    (void)accR;

    // ---- four channel chunks of 4 ----
    for (int chunk = 0; chunk < 4; ++chunk) {
        const int ch0 = chunk * CC;

        __syncthreads();   // protect prior-iter tile reads (and coeff writes @chunk 0)

        // ---- stage pre-packed pair tile: warp-per-row mapping, no div/mod ----
        // 24 (c,r) slot rows; warp w (0..7) takes rows w, w+8, w+16.
        {
            const float* xb = x + ((size_t)(b * C_ + ch0)) * (H_ * W_);
            #pragma unroll
            for (int j = 0; j < 3; ++j) {
                const int row = ty + j * 8;          // 0..23
                const int c   = row / NR;            // 0..3 (compile-time-ish: row constant per j? no)
                const int r   = row - c * NR;        // 0..5
                const int gya = gy0 + r - 1;
                const int gyb = gya + 4;
                double* dst = spx + row * XPITCH;
                const float* rowa = xb + c * (H_ * W_) + gya * W_;
                const float* rowb = xb + c * (H_ * W_) + gyb * W_;
                const bool oka = (unsigned)gya < H_;
                const bool okb = (unsigned)gyb < H_;
                #pragma unroll
                for (int pass = 0; pass < 3; ++pass) {
                    const int p = tx + pass * 32;
                    if (p < 66) {
                        const int gx = p - 1;
                        const bool okx = (unsigned)gx < W_;
                        float va = (oka && okx) ? rowa[gx] : 0.f;
                        float vb = (okb && okx) ? rowb[gx] : 0.f;
                        dst[p] = __longlong_as_double((long long)pack2(va, vb));
                    }
                }
            }
        }

        __syncthreads();

        // ---- rational conv accumulate ----
        // Thread: row-pair pr, column col. Two independent acc chains via k-split:
        // accL takes bb=0,1 taps; accR takes bb=2 (and both merged at end).
        #pragma unroll 2
        for (int c = 0; c < CC; ++c) {
            const double*  xc = spx + c * SLOT + pr * XPITCH + col;
            const double2* cp = (const double2*)(scf + (ch0 + c) * 90);
            #pragma unroll
            for (int a = 0; a < 3; ++a) {
                // three taps on this row: bb = 0,1,2 at cols col-1..col+1 (phys col..col+2)
                const ull xp0 = __double_as_longlong(xc[a * XPITCH + 0]);
                const ull xp1 = __double_as_longlong(xc[a * XPITCH + 1]);
                const ull xp2 = __double_as_longlong(xc[a * XPITCH + 2]);
                {
                    const int k = a * 3;
                    const double2 d0 = cp[k * 5 + 0];
                    const double2 d1 = cp[k * 5 + 1];
                    const double2 d2 = cp[k * 5 + 2];
                    const double2 d3 = cp[k * 5 + 3];
                    const double2 d4 = cp[k * 5 + 4];
                    const double2 e0 = cp[(k + 1) * 5 + 0];
                    const double2 e1 = cp[(k + 1) * 5 + 1];
                    const double2 e2 = cp[(k + 1) * 5 + 2];
                    const double2 e3 = cp[(k + 1) * 5 + 3];
                    const double2 e4 = cp[(k + 1) * 5 + 4];
                    // interleave taps k (xp0, coeffs d*) and k+1 (xp1, coeffs e*)
                    ull PL = fma2(__double_as_longlong(d0.x), xp0, __double_as_longlong(d0.y));
                    ull PR = fma2(__double_as_longlong(e0.x), xp1, __double_as_longlong(e0.y));
                    ull SL = fma2(__double_as_longlong(d3.x), xp0, __double_as_longlong(d3.y));
                    ull SR = fma2(__double_as_longlong(e3.x), xp1, __double_as_longlong(e3.y));
                    PL = fma2(PL, xp0, __double_as_longlong(d1.x));
                    PR = fma2(PR, xp1, __double_as_longlong(e1.x));
                    SL = fma2(SL, xp0, __double_as_longlong(d4.x));
                    SR = fma2(SR, xp1, __double_as_longlong(e4.x));
                    PL = fma2(PL, xp0, __double_as_longlong(d1.y));
                    PR = fma2(PR, xp1, __double_as_longlong(e1.y));
                    SL = fma2(SL, xp0, __double_as_longlong(d4.y));
                    SR = fma2(SR, xp1, __double_as_longlong(e4.y));
                    PL = fma2(PL, xp0, __double_as_longlong(d2.x));
                    PR = fma2(PR, xp1, __double_as_longlong(e2.x));
                    const ull SxL = mul2(SL, xp0);
                    const ull SxR = mul2(SR, xp1);
                    PL = fma2(PL, xp0, __double_as_longlong(d2.y));
                    PR = fma2(PR, xp1, __double_as_longlong(e2.y));
                    float sL0, sL1, sR0, sR1;
                    unpack2(SxL, sL0, sL1);
                    unpack2(SxR, sR0, sR1);
                    const float rL0 = frcp(1.0f + fabsf(sL0));
                    const float rL1 = frcp(1.0f + fabsf(sL1));
                    const float rR0 = frcp(1.0f + fabsf(sR0));
                    const float rR1 = frcp(1.0f + fabsf(sR1));
                    accL = fma2(PL, pack2(rL0, rL1), accL);
                    accR = fma2(PR, pack2(rR0, rR1), accR);
                }
                {
                    // tap k+2 (xp2) alone, into accL
                    const int k = a * 3 + 2;
                    const double2 d0 = cp[k * 5 + 0];
                    const double2 d1 = cp[k * 5 + 1];
                    const double2 d2 = cp[k * 5 + 2];
                    const double2 d3 = cp[k * 5 + 3];
                    const double2 d4 = cp[k * 5 + 4];
                    ull P = fma2(__double_as_longlong(d0.x), xp2, __double_as_longlong(d0.y));
                    ull S = fma2(__double_as_longlong(d3.x), xp2, __double_as_longlong(d3.y));
                    P = fma2(P, xp2, __double_as_longlong(d1.x));
                    S = fma2(S, xp2, __double_as_longlong(d4.x));
                    P = fma2(P, xp2, __double_as_longlong(d1.y));
                    S = fma2(S, xp2, __double_as_longlong(d4.y));
                    P = fma2(P, xp2, __double_as_longlong(d2.x));
                    const ull Sx = mul2(S, xp2);
                    P = fma2(P, xp2, __double_as_longlong(d2.y));
                    float s0, s1;
                    unpack2(Sx, s0, s1);
                    const float r0 = frcp(1.0f + fabsf(s0));
                    const float r1 = frcp(1.0f + fabsf(s1));
                    accL = fma2(P, pack2(r0, r1), accL);
                }
            }
        }
    }

    // merge the two accumulator chains (lane-wise add)
    float aL0, aL1, aR0, aR1;
    unpack2(accL, aL0, aL1);
    unpack2(accR, aR0, aR1);
    const float o0 = aL0 + aR0;
    const float o1 = aL1 + aR1;

    // ---- write (B,F,H,W): rows gy0+pr and gy0+pr+4 at column col ----
    float* op = out + ((size_t)blockIdx.z * H_ + gy0 + pr) * W_ + col;
    op[0]              = o0;
    op[(size_t)4 * W_] = o1;
}

extern "C" void kernel_launch(void* const* d_in, const int* in_sizes, int n_in,
                              void* d_out, int out_size) {
    const float* x      = (const float*)d_in[0];
    const float* nums   = (const float*)d_in[1];
    const float* denoms = (const float*)d_in[2];
    float* out = (float*)d_out;

    dim3 grid(1, H_ / 8, B_ * F_);   // 1 x 8 x 128 = 1024 blocks
    dim3 block(32, 8);
    kaconv_kernel<<<grid, block>>>(x, nums, denoms, out);
}